// round 3
// baseline (speedup 1.0000x reference)
#include <cuda_runtime.h>
#include <cuda_fp16.h>
#include <cstdint>
#include <math.h>

// ---------------- problem constants ----------------
#define S_LEN   8192
#define D_DIM   4096
#define H_HEADS 8
#define G_GRP   4
#define HD_DIM  128
#define NOUT    5120   // 4096 q cols + 1024 k cols

// ---------------- scratch (device globals: allocation-free) ----------------
__device__ __half g_hsH[S_LEN * D_DIM];          // fp16 hidden states
__device__ __half g_wH[NOUT * D_DIM];            // fp16 packed [q_w;k_w]
__device__ float  g_C[(size_t)S_LEN * NOUT];     // fp32 GEMM output

// ---------------- GEMM config ----------------
static constexpr int BM = 128;
static constexpr int BN = 256;
static constexpr int BK = 32;                  // halves per K stage
static constexpr int NKITER = D_DIM / BK;      // 128
static constexpr int STAGES = 4;
static constexpr int THREADS = 512;

// SMEM "panel" layout: panel p holds halves k in [8p, 8p+8) for all rows.
// addr(row,p) = p*PANEL + row*16.  PANEL = rows*16 + 32 so that the panel
// stride is ≡ 32 mod 128 bytes -> cp.async stores and ldmatrix reads are
// bank-conflict-free with no XOR swizzle.
static constexpr int PANEL_A = BM * 16 + 32;   // 2080
static constexpr int ASTAGE  = 4 * PANEL_A;    // 8320
static constexpr int PANEL_B = BN * 16 + 32;   // 4128
static constexpr int BSTAGE  = 4 * PANEL_B;    // 16512
static constexpr int STAGE   = ASTAGE + BSTAGE;        // 24832
static constexpr int SMEM_TOTAL = STAGES * STAGE;      // 99328

__device__ __forceinline__ uint32_t smem_u32(const void* p) {
    uint32_t a;
    asm("{ .reg .u64 t; cvta.to.shared.u64 t, %1; cvt.u32.u64 %0, t; }" : "=r"(a) : "l"(p));
    return a;
}

#define CP_ASYNC_16(smem_addr, gptr) \
    asm volatile("cp.async.cg.shared.global [%0], [%1], 16;" :: "r"(smem_addr), "l"(gptr) : "memory")
#define CP_ASYNC_COMMIT() asm volatile("cp.async.commit_group;" ::: "memory")
#define CP_ASYNC_WAIT2()  asm volatile("cp.async.wait_group 2;" ::: "memory")
#define CP_ASYNC_WAIT0()  asm volatile("cp.async.wait_group 0;" ::: "memory")

#define LDSM_X4(r0, r1, r2, r3, addr) \
    asm volatile("ldmatrix.sync.aligned.m8n8.x4.shared.b16 {%0,%1,%2,%3}, [%4];" \
        : "=r"(r0), "=r"(r1), "=r"(r2), "=r"(r3) : "r"(addr))

#define MMA_16816(c, a, b) \
    asm volatile("mma.sync.aligned.m16n8k16.row.col.f32.f16.f16.f32 " \
        "{%0,%1,%2,%3}, {%4,%5,%6,%7}, {%8,%9}, {%0,%1,%2,%3};" \
        : "+f"((c)[0]), "+f"((c)[1]), "+f"((c)[2]), "+f"((c)[3]) \
        : "r"((a)[0]), "r"((a)[1]), "r"((a)[2]), "r"((a)[3]), "r"((b)[0]), "r"((b)[1]))

// ---------------- conversion kernels (fp32 -> fp16) ----------------
__global__ void __launch_bounds__(256) cvt_hs_kernel(const float* __restrict__ src) {
    int i = (blockIdx.x * 256 + threadIdx.x) * 4;
    float4 v = *reinterpret_cast<const float4*>(src + i);
    *reinterpret_cast<__half2*>(g_hsH + i)     = __floats2half2_rn(v.x, v.y);
    *reinterpret_cast<__half2*>(g_hsH + i + 2) = __floats2half2_rn(v.z, v.w);
}
__global__ void __launch_bounds__(256) cvt_qw_kernel(const float* __restrict__ src) {
    int i = (blockIdx.x * 256 + threadIdx.x) * 4;
    float4 v = *reinterpret_cast<const float4*>(src + i);
    *reinterpret_cast<__half2*>(g_wH + i)     = __floats2half2_rn(v.x, v.y);
    *reinterpret_cast<__half2*>(g_wH + i + 2) = __floats2half2_rn(v.z, v.w);
}
__global__ void __launch_bounds__(256) cvt_kw_kernel(const float* __restrict__ src) {
    int i = (blockIdx.x * 256 + threadIdx.x) * 4;
    float4 v = *reinterpret_cast<const float4*>(src + i);
    __half* dst = g_wH + 4096 * 4096;
    *reinterpret_cast<__half2*>(dst + i)     = __floats2half2_rn(v.x, v.y);
    *reinterpret_cast<__half2*>(dst + i + 2) = __floats2half2_rn(v.z, v.w);
}

// ---------------- GEMM: C = hsH @ wH^T (fp16 in, fp32 accum/out) ----------------
__device__ __forceinline__ void load_stage(uint32_t sb, char* smem, int st, int kt,
                                           const __half* Abase, const __half* Bbase, int tid) {
    const int k0 = kt * BK;
    const uint32_t stbase = sb + st * STAGE;
    {
        int row = tid >> 2, p = tid & 3;
        uint32_t sa = stbase + p * PANEL_A + row * 16;
        const __half* g = Abase + (size_t)row * D_DIM + k0 + p * 8;
        CP_ASYNC_16(sa, g);
    }
#pragma unroll
    for (int j = 0; j < 2; j++) {
        int idx = tid + j * THREADS;
        int row = idx >> 2, p = idx & 3;
        uint32_t sa = stbase + ASTAGE + p * PANEL_B + row * 16;
        const __half* g = Bbase + (size_t)row * D_DIM + k0 + p * 8;
        CP_ASYNC_16(sa, g);
    }
}

__global__ void __launch_bounds__(THREADS, 1) gemm_kernel() {
    extern __shared__ char smem[];
    const uint32_t sb = smem_u32(smem);
    const int tid  = threadIdx.x;
    const int wid  = tid >> 5;
    const int lane = tid & 31;
    const int m0 = blockIdx.y * BM;
    const int n0 = blockIdx.x * BN;

    const int wm = wid & 3;    // 4 warps over M (32 rows each)
    const int wn = wid >> 2;   // 4 warps over N (64 cols each)

    const __half* Abase = g_hsH + (size_t)m0 * D_DIM;
    const __half* Bbase = g_wH  + (size_t)n0 * D_DIM;

    float c[2][8][4];
#pragma unroll
    for (int i = 0; i < 2; i++)
#pragma unroll
        for (int j = 0; j < 8; j++)
#pragma unroll
            for (int k = 0; k < 4; k++) c[i][j][k] = 0.0f;

    // prologue: stages 0..2
#pragma unroll
    for (int s = 0; s < STAGES - 1; s++) {
        load_stage(sb, smem, s, s, Abase, Bbase, tid);
        CP_ASYNC_COMMIT();
    }

    // per-warp ldmatrix base addresses (lane-dependent parts)
    const int a_row = wm * 32 + (lane & 15);       // + mt*16
    const int a_pan = (lane >> 4);                 // + ks*2
    const int b_row = wn * 64 + (lane & 7) + ((lane >> 4) << 3);  // + u*16
    const int b_pan = ((lane >> 3) & 1);           // + ks*2

    for (int kt = 0; kt < NKITER; kt++) {
        CP_ASYNC_WAIT2();
        __syncthreads();

        if (kt + STAGES - 1 < NKITER)
            load_stage(sb, smem, (kt + STAGES - 1) & (STAGES - 1), kt + STAGES - 1, Abase, Bbase, tid);
        CP_ASYNC_COMMIT();

        const uint32_t base = sb + (kt & (STAGES - 1)) * STAGE;
#pragma unroll
        for (int ks = 0; ks < 2; ks++) {
            const int p0 = ks * 2;
            uint32_t a[2][4];
#pragma unroll
            for (int mt = 0; mt < 2; mt++) {
                uint32_t addr = base + (p0 + a_pan) * PANEL_A + (a_row + mt * 16) * 16;
                LDSM_X4(a[mt][0], a[mt][1], a[mt][2], a[mt][3], addr);
            }
            uint32_t b[8][2];
#pragma unroll
            for (int u = 0; u < 4; u++) {
                uint32_t addr = base + ASTAGE + (p0 + b_pan) * PANEL_B + (b_row + u * 16) * 16;
                LDSM_X4(b[2 * u][0], b[2 * u][1], b[2 * u + 1][0], b[2 * u + 1][1], addr);
            }
#pragma unroll
            for (int mt = 0; mt < 2; mt++)
#pragma unroll
                for (int nt = 0; nt < 8; nt++)
                    MMA_16816(c[mt][nt], a[mt], b[nt]);
        }
        __syncthreads();
    }

    // epilogue: write fp32 C
    const int g = lane >> 2, t = lane & 3;
#pragma unroll
    for (int mt = 0; mt < 2; mt++) {
        const int m = m0 + wm * 32 + mt * 16 + g;
        float* r0 = g_C + (size_t)m * NOUT + n0 + wn * 64 + t * 2;
        float* r1 = r0 + 8 * NOUT;
#pragma unroll
        for (int nt = 0; nt < 8; nt++) {
            *reinterpret_cast<float2*>(r0 + nt * 8) = make_float2(c[mt][nt][0], c[mt][nt][1]);
            *reinterpret_cast<float2*>(r1 + nt * 8) = make_float2(c[mt][nt][2], c[mt][nt][3]);
        }
    }
}

// ---------------- epilogue: RMSNorm + logits + sigmoid score ----------------
__device__ __forceinline__ float wsum(float v) {
#pragma unroll
    for (int o = 16; o > 0; o >>= 1) v += __shfl_xor_sync(0xffffffffu, v, o);
    return v;
}

__global__ void __launch_bounds__(256) score_kernel(
    const float* __restrict__ qb, const float* __restrict__ qnw,
    const float* __restrict__ knw, const float* __restrict__ kbase,
    const float* __restrict__ bvec, float* __restrict__ out) {
    const int w = blockIdx.x * 8 + (threadIdx.x >> 5);
    const int lane = threadIdx.x & 31;
    const int s = w >> 3;
    const int h = w & 7;
    const float* Crow = g_C + (size_t)s * NOUT;

    float4 k4  = *reinterpret_cast<const float4*>(Crow + 4096 + h * HD_DIM + lane * 4);
    float4 kw4 = *reinterpret_cast<const float4*>(knw + lane * 4);
    float ssk = wsum(k4.x * k4.x + k4.y * k4.y + k4.z * k4.z + k4.w * k4.w);
    float kn = rsqrtf(ssk * (1.0f / HD_DIM) + 1e-6f);
    float khx = k4.x * kn * kw4.x;
    float khy = k4.y * kn * kw4.y;
    float khz = k4.z * kn * kw4.z;
    float khw = k4.w * kn * kw4.w;

    float4 kb4 = *reinterpret_cast<const float4*>(kbase + h * HD_DIM + lane * 4);
    float4 qn4 = *reinterpret_cast<const float4*>(qnw + lane * 4);
    const float invs = 0.08838834764831843f;  // 1/sqrt(128)

    float acc = 0.0f;
#pragma unroll
    for (int gg = 0; gg < G_GRP; ++gg) {
        float4 q4  = *reinterpret_cast<const float4*>(Crow + h * 512 + gg * 128 + lane * 4);
        float4 qb4 = *reinterpret_cast<const float4*>(qb + h * 512 + gg * 128 + lane * 4);
        float qx = q4.x + qb4.x, qy = q4.y + qb4.y, qz = q4.z + qb4.z, qw = q4.w + qb4.w;
        float ssq = wsum(qx * qx + qy * qy + qz * qz + qw * qw);
        float qs = rsqrtf(ssq * (1.0f / HD_DIM) + 1e-6f);
        qx *= qs * qn4.x; qy *= qs * qn4.y; qz *= qs * qn4.z; qw *= qs * qn4.w;
        float dm = wsum(qx * khx + qy * khy + qz * khz + qw * khw);
        float db = wsum(qx * kb4.x + qy * kb4.y + qz * kb4.z + qw * kb4.w);
        float logit = dm * invs + bvec[h * G_GRP + gg];
        float base  = db * invs;
        acc += 1.0f / (1.0f + expf(base - logit));
    }
    if (lane == 0) out[h * S_LEN + s] = acc * 0.25f;
}

// ---------------- launch ----------------
extern "C" void kernel_launch(void* const* d_in, const int* in_sizes, int n_in,
                              void* d_out, int out_size) {
    (void)in_sizes; (void)n_in; (void)out_size;
    const float* hs    = (const float*)d_in[0];
    const float* qw    = (const float*)d_in[1];
    const float* qb    = (const float*)d_in[2];
    const float* kw    = (const float*)d_in[3];
    const float* qnw   = (const float*)d_in[4];
    const float* knw   = (const float*)d_in[5];
    const float* kbase = (const float*)d_in[6];
    const float* bvec  = (const float*)d_in[7];
    float* out = (float*)d_out;

    cvt_hs_kernel<<<S_LEN * D_DIM / 1024, 256>>>(hs);
    cvt_qw_kernel<<<4096 * 4096 / 1024, 256>>>(qw);
    cvt_kw_kernel<<<1024 * 4096 / 1024, 256>>>(kw);

    cudaFuncSetAttribute(gemm_kernel, cudaFuncAttributeMaxDynamicSharedMemorySize, SMEM_TOTAL);
    gemm_kernel<<<dim3(NOUT / BN, S_LEN / BM), THREADS, SMEM_TOTAL>>>();

    score_kernel<<<S_LEN * H_HEADS / 8, 256>>>(qb, qnw, knw, kbase, bvec, out);
}

// round 4
// speedup vs baseline: 1.0204x; 1.0204x over previous
#include <cuda_runtime.h>
#include <cuda_fp16.h>
#include <cstdint>
#include <math.h>

// ---------------- problem constants ----------------
#define S_LEN   8192
#define D_DIM   4096
#define H_HEADS 8
#define G_GRP   4
#define HD_DIM  128
#define NOUT    5120   // 4096 q cols + 1024 k cols

// ---------------- scratch (device globals: allocation-free) ----------------
__device__ __half g_hsH[S_LEN * D_DIM];          // fp16 hidden states
__device__ __half g_wH[NOUT * D_DIM];            // fp16 packed [q_w;k_w]
__device__ float  g_C[(size_t)S_LEN * NOUT];     // fp32 GEMM output

// ---------------- GEMM config ----------------
static constexpr int BM = 128;
static constexpr int BN = 256;
static constexpr int BK = 64;                  // halves per K stage
static constexpr int NKITER = D_DIM / BK;      // 64
static constexpr int STAGES = 4;
static constexpr int THREADS = 512;

// SMEM "panel" layout: panel p holds halves k in [8p, 8p+8) for all rows.
// addr(row,p) = p*PANEL + row*16.  PANEL = rows*16 + 32 keeps the panel
// stride ≡ 32 mod 128 bytes -> cp.async stores and ldmatrix reads are
// bank-conflict-free with no XOR swizzle.
static constexpr int PANEL_A = BM * 16 + 32;   // 2080
static constexpr int ASTAGE  = 8 * PANEL_A;    // 16640
static constexpr int PANEL_B = BN * 16 + 32;   // 4128
static constexpr int BSTAGE  = 8 * PANEL_B;    // 33024
static constexpr int STAGE   = ASTAGE + BSTAGE;        // 49664
static constexpr int SMEM_TOTAL = STAGES * STAGE;      // 198656

__device__ __forceinline__ uint32_t smem_u32(const void* p) {
    uint32_t a;
    asm("{ .reg .u64 t; cvta.to.shared.u64 t, %1; cvt.u32.u64 %0, t; }" : "=r"(a) : "l"(p));
    return a;
}

#define CP_ASYNC_16(smem_addr, gptr) \
    asm volatile("cp.async.cg.shared.global [%0], [%1], 16;" :: "r"(smem_addr), "l"(gptr) : "memory")
#define CP_ASYNC_COMMIT() asm volatile("cp.async.commit_group;" ::: "memory")
#define CP_ASYNC_WAIT2()  asm volatile("cp.async.wait_group 2;" ::: "memory")

#define LDSM_X4(r0, r1, r2, r3, addr) \
    asm volatile("ldmatrix.sync.aligned.m8n8.x4.shared.b16 {%0,%1,%2,%3}, [%4];" \
        : "=r"(r0), "=r"(r1), "=r"(r2), "=r"(r3) : "r"(addr))

#define MMA_16816(c, a, b) \
    asm volatile("mma.sync.aligned.m16n8k16.row.col.f32.f16.f16.f32 " \
        "{%0,%1,%2,%3}, {%4,%5,%6,%7}, {%8,%9}, {%0,%1,%2,%3};" \
        : "+f"((c)[0]), "+f"((c)[1]), "+f"((c)[2]), "+f"((c)[3]) \
        : "r"((a)[0]), "r"((a)[1]), "r"((a)[2]), "r"((a)[3]), "r"((b)[0]), "r"((b)[1]))

// ---------------- conversion kernels (fp32 -> fp16) ----------------
__global__ void __launch_bounds__(256) cvt_hs_kernel(const float* __restrict__ src) {
    int i = (blockIdx.x * 256 + threadIdx.x) * 4;
    float4 v = *reinterpret_cast<const float4*>(src + i);
    *reinterpret_cast<__half2*>(g_hsH + i)     = __floats2half2_rn(v.x, v.y);
    *reinterpret_cast<__half2*>(g_hsH + i + 2) = __floats2half2_rn(v.z, v.w);
}
__global__ void __launch_bounds__(256) cvt_qw_kernel(const float* __restrict__ src) {
    int i = (blockIdx.x * 256 + threadIdx.x) * 4;
    float4 v = *reinterpret_cast<const float4*>(src + i);
    *reinterpret_cast<__half2*>(g_wH + i)     = __floats2half2_rn(v.x, v.y);
    *reinterpret_cast<__half2*>(g_wH + i + 2) = __floats2half2_rn(v.z, v.w);
}
__global__ void __launch_bounds__(256) cvt_kw_kernel(const float* __restrict__ src) {
    int i = (blockIdx.x * 256 + threadIdx.x) * 4;
    float4 v = *reinterpret_cast<const float4*>(src + i);
    __half* dst = g_wH + 4096 * 4096;
    *reinterpret_cast<__half2*>(dst + i)     = __floats2half2_rn(v.x, v.y);
    *reinterpret_cast<__half2*>(dst + i + 2) = __floats2half2_rn(v.z, v.w);
}

// ---------------- GEMM: C = hsH @ wH^T (fp16 in, fp32 accum/out) ----------------
__device__ __forceinline__ void load_stage(uint32_t sb, int st, int kt,
                                           const __half* Abase, const __half* Bbase, int tid) {
    const int k0 = kt * BK;
    const uint32_t stbase = sb + st * STAGE;
    // A: 128 rows x 8 panels = 1024 chunks / 512 threads = 2 each
#pragma unroll
    for (int j = 0; j < 2; j++) {
        int idx = tid + j * THREADS;
        int row = idx >> 3, p = idx & 7;
        uint32_t sa = stbase + p * PANEL_A + row * 16;
        const __half* g = Abase + (size_t)row * D_DIM + k0 + p * 8;
        CP_ASYNC_16(sa, g);
    }
    // B: 256 rows x 8 panels = 2048 chunks / 512 threads = 4 each
#pragma unroll
    for (int j = 0; j < 4; j++) {
        int idx = tid + j * THREADS;
        int row = idx >> 3, p = idx & 7;
        uint32_t sa = stbase + ASTAGE + p * PANEL_B + row * 16;
        const __half* g = Bbase + (size_t)row * D_DIM + k0 + p * 8;
        CP_ASYNC_16(sa, g);
    }
}

__global__ void __launch_bounds__(THREADS, 1) gemm_kernel() {
    extern __shared__ char smem[];
    const uint32_t sb = smem_u32(smem);
    const int tid  = threadIdx.x;
    const int wid  = tid >> 5;
    const int lane = tid & 31;
    const int m0 = blockIdx.y * BM;
    const int n0 = blockIdx.x * BN;

    const int wm = wid & 3;    // 4 warps over M (32 rows each)
    const int wn = wid >> 2;   // 4 warps over N (64 cols each)

    const __half* Abase = g_hsH + (size_t)m0 * D_DIM;
    const __half* Bbase = g_wH  + (size_t)n0 * D_DIM;

    float c[2][8][4];
#pragma unroll
    for (int i = 0; i < 2; i++)
#pragma unroll
        for (int j = 0; j < 8; j++)
#pragma unroll
            for (int k = 0; k < 4; k++) c[i][j][k] = 0.0f;

    // prologue: stages 0..2
#pragma unroll
    for (int s = 0; s < STAGES - 1; s++) {
        load_stage(sb, s, s, Abase, Bbase, tid);
        CP_ASYNC_COMMIT();
    }

    // per-warp ldmatrix lane-dependent address parts
    const int a_row = wm * 32 + (lane & 15);                       // + mt*16
    const int a_pan = (lane >> 4);                                 // + ks*2
    const int b_row = wn * 64 + (lane & 7) + ((lane >> 4) << 3);   // + u*16
    const int b_pan = ((lane >> 3) & 1);                           // + ks*2

    for (int kt = 0; kt < NKITER; kt++) {
        CP_ASYNC_WAIT2();          // stage kt resident
        __syncthreads();           // all warps done with stage (kt+3)&3 == (kt-1)&3

        if (kt + STAGES - 1 < NKITER)
            load_stage(sb, (kt + STAGES - 1) & (STAGES - 1), kt + STAGES - 1, Abase, Bbase, tid);
        CP_ASYNC_COMMIT();

        const uint32_t base = sb + (kt & (STAGES - 1)) * STAGE;
#pragma unroll
        for (int ks = 0; ks < 4; ks++) {
            const int p0 = ks * 2;
            uint32_t a[2][4];
#pragma unroll
            for (int mt = 0; mt < 2; mt++) {
                uint32_t addr = base + (p0 + a_pan) * PANEL_A + (a_row + mt * 16) * 16;
                LDSM_X4(a[mt][0], a[mt][1], a[mt][2], a[mt][3], addr);
            }
            uint32_t b[8][2];
#pragma unroll
            for (int u = 0; u < 4; u++) {
                uint32_t addr = base + ASTAGE + (p0 + b_pan) * PANEL_B + (b_row + u * 16) * 16;
                LDSM_X4(b[2 * u][0], b[2 * u][1], b[2 * u + 1][0], b[2 * u + 1][1], addr);
            }
#pragma unroll
            for (int mt = 0; mt < 2; mt++)
#pragma unroll
                for (int nt = 0; nt < 8; nt++)
                    MMA_16816(c[mt][nt], a[mt], b[nt]);
        }
        // no trailing barrier: the top-of-loop barrier + register-resident
        // ldmatrix results make the next iteration's overwrite safe
    }

    // epilogue: write fp32 C
    const int g = lane >> 2, t = lane & 3;
#pragma unroll
    for (int mt = 0; mt < 2; mt++) {
        const int m = m0 + wm * 32 + mt * 16 + g;
        float* r0 = g_C + (size_t)m * NOUT + n0 + wn * 64 + t * 2;
        float* r1 = r0 + 8 * NOUT;
#pragma unroll
        for (int nt = 0; nt < 8; nt++) {
            *reinterpret_cast<float2*>(r0 + nt * 8) = make_float2(c[mt][nt][0], c[mt][nt][1]);
            *reinterpret_cast<float2*>(r1 + nt * 8) = make_float2(c[mt][nt][2], c[mt][nt][3]);
        }
    }
}

// ---------------- epilogue: RMSNorm + logits + sigmoid score ----------------
__device__ __forceinline__ float wsum(float v) {
#pragma unroll
    for (int o = 16; o > 0; o >>= 1) v += __shfl_xor_sync(0xffffffffu, v, o);
    return v;
}

__global__ void __launch_bounds__(256) score_kernel(
    const float* __restrict__ qb, const float* __restrict__ qnw,
    const float* __restrict__ knw, const float* __restrict__ kbase,
    const float* __restrict__ bvec, float* __restrict__ out) {
    const int w = blockIdx.x * 8 + (threadIdx.x >> 5);
    const int lane = threadIdx.x & 31;
    const int s = w >> 3;
    const int h = w & 7;
    const float* Crow = g_C + (size_t)s * NOUT;

    float4 k4  = *reinterpret_cast<const float4*>(Crow + 4096 + h * HD_DIM + lane * 4);
    float4 kw4 = *reinterpret_cast<const float4*>(knw + lane * 4);
    float ssk = wsum(k4.x * k4.x + k4.y * k4.y + k4.z * k4.z + k4.w * k4.w);
    float kn = rsqrtf(ssk * (1.0f / HD_DIM) + 1e-6f);
    float khx = k4.x * kn * kw4.x;
    float khy = k4.y * kn * kw4.y;
    float khz = k4.z * kn * kw4.z;
    float khw = k4.w * kn * kw4.w;

    float4 kb4 = *reinterpret_cast<const float4*>(kbase + h * HD_DIM + lane * 4);
    float4 qn4 = *reinterpret_cast<const float4*>(qnw + lane * 4);
    const float invs = 0.08838834764831843f;  // 1/sqrt(128)

    float acc = 0.0f;
#pragma unroll
    for (int gg = 0; gg < G_GRP; ++gg) {
        float4 q4  = *reinterpret_cast<const float4*>(Crow + h * 512 + gg * 128 + lane * 4);
        float4 qb4 = *reinterpret_cast<const float4*>(qb + h * 512 + gg * 128 + lane * 4);
        float qx = q4.x + qb4.x, qy = q4.y + qb4.y, qz = q4.z + qb4.z, qw = q4.w + qb4.w;
        float ssq = wsum(qx * qx + qy * qy + qz * qz + qw * qw);
        float qs = rsqrtf(ssq * (1.0f / HD_DIM) + 1e-6f);
        qx *= qs * qn4.x; qy *= qs * qn4.y; qz *= qs * qn4.z; qw *= qs * qn4.w;
        float dm = wsum(qx * khx + qy * khy + qz * khz + qw * khw);
        float db = wsum(qx * kb4.x + qy * kb4.y + qz * kb4.z + qw * kb4.w);
        float logit = dm * invs + bvec[h * G_GRP + gg];
        float base  = db * invs;
        acc += 1.0f / (1.0f + expf(base - logit));
    }
    if (lane == 0) out[h * S_LEN + s] = acc * 0.25f;
}

// ---------------- launch ----------------
extern "C" void kernel_launch(void* const* d_in, const int* in_sizes, int n_in,
                              void* d_out, int out_size) {
    (void)in_sizes; (void)n_in; (void)out_size;
    const float* hs    = (const float*)d_in[0];
    const float* qw    = (const float*)d_in[1];
    const float* qb    = (const float*)d_in[2];
    const float* kw    = (const float*)d_in[3];
    const float* qnw   = (const float*)d_in[4];
    const float* knw   = (const float*)d_in[5];
    const float* kbase = (const float*)d_in[6];
    const float* bvec  = (const float*)d_in[7];
    float* out = (float*)d_out;

    cvt_hs_kernel<<<S_LEN * D_DIM / 1024, 256>>>(hs);
    cvt_qw_kernel<<<4096 * 4096 / 1024, 256>>>(qw);
    cvt_kw_kernel<<<1024 * 4096 / 1024, 256>>>(kw);

    cudaFuncSetAttribute(gemm_kernel, cudaFuncAttributeMaxDynamicSharedMemorySize, SMEM_TOTAL);
    gemm_kernel<<<dim3(NOUT / BN, S_LEN / BM), THREADS, SMEM_TOTAL>>>();

    score_kernel<<<S_LEN * H_HEADS / 8, 256>>>(qb, qnw, knw, kbase, bvec, out);
}